// round 3
// baseline (speedup 1.0000x reference)
#include <cuda_runtime.h>
#include <cuda_bf16.h>
#include <math.h>

// pred/target: (32, 3, 512, 512) fp32 -> scalar fp32 mean |sobel(gray(p)) - sobel(gray(t))|
#define B      32
#define H      512
#define W      512
#define PLANE  (H * W)
#define IMG    (3 * PLANE)
#define NPIX   (B * PLANE)          // 8388608

#define RT     32                   // output rows per block
#define STRIPS 2                    // vertical strips of 256 cols
#define SW     256
#define TILESY (H / RT)             // 16
#define NBLK   (B * TILESY * STRIPS) // 1024
#define TPB    64                   // 2 warps, each covers 128 cols
#define FULLM  0xffffffffu

__device__ float        g_partials[NBLK];
__device__ unsigned int g_count = 0;

__device__ __forceinline__ float fsqrt_approx(float x) {
    float r; asm("sqrt.approx.f32 %0, %1;" : "=f"(r) : "f"(x)); return r;
}

__device__ __forceinline__ float gray1(const float* __restrict__ p, int o) {
    return 0.299f * p[o] + 0.587f * p[o + PLANE] + 0.114f * p[o + 2 * PLANE];
}

// Load one gray row segment into a 6-wide window [cx-1 .. cx+4].
// Interior neighbors via warp shuffle; warp/strip/image boundaries via scalar loads.
__device__ __forceinline__ void load_row(const float* __restrict__ img,
                                         int gy, int cx, float w[6])
{
    if ((unsigned)gy >= (unsigned)H) {
        #pragma unroll
        for (int i = 0; i < 6; i++) w[i] = 0.f;
        return;
    }
    const int o = gy * W + cx;
    const float4 r  = *(const float4*)(img + o);
    const float4 g  = *(const float4*)(img + PLANE + o);
    const float4 bl = *(const float4*)(img + 2 * PLANE + o);
    const float g0 = 0.299f * r.x + 0.587f * g.x + 0.114f * bl.x;
    const float g1 = 0.299f * r.y + 0.587f * g.y + 0.114f * bl.y;
    const float g2 = 0.299f * r.z + 0.587f * g.z + 0.114f * bl.z;
    const float g3 = 0.299f * r.w + 0.587f * g.w + 0.114f * bl.w;
    float l  = __shfl_up_sync(FULLM, g3, 1);     // lane-1's last col
    float rr = __shfl_down_sync(FULLM, g0, 1);   // lane+1's first col
    const int lane = threadIdx.x & 31;
    if (lane == 0)  l  = (cx == 0)     ? 0.f : gray1(img, o - 1);
    if (lane == 31) rr = (cx + 4 >= W) ? 0.f : gray1(img, o + 4);
    w[0] = l; w[1] = g0; w[2] = g1; w[3] = g2; w[4] = g3; w[5] = rr;
}

// Sobel magnitudes for 4 columns given top/mid/bot 6-wide windows.
__device__ __forceinline__ void mag4(const float* t, const float* m,
                                     const float* bo, float o[4])
{
    #pragma unroll
    for (int j = 0; j < 4; j++) {
        float ex = (t[j + 2] - t[j]) + 2.f * (m[j + 2] - m[j]) + (bo[j + 2] - bo[j]);
        float ey = (bo[j] - t[j]) + 2.f * (bo[j + 1] - t[j + 1]) + (bo[j + 2] - t[j + 2]);
        o[j] = fsqrt_approx(ex * ex + ey * ey);
    }
}

// One row-step with literal rotation indices (A=top, M=mid, C=new bottom).
#define STEP(A, M, C) do {                                                  \
    load_row(pr, gy, cx, wp[C]);                                            \
    load_row(tr, gy, cx, wt[C]);                                            \
    float mpv[4], mtv[4];                                                   \
    mag4(wp[A], wp[M], wp[C], mpv);                                         \
    mag4(wt[A], wt[M], wt[C], mtv);                                         \
    acc += fabsf(mpv[0] - mtv[0]) + fabsf(mpv[1] - mtv[1])                  \
         + fabsf(mpv[2] - mtv[2]) + fabsf(mpv[3] - mtv[3]);                 \
    gy++;                                                                   \
} while (0)

__global__ __launch_bounds__(TPB, 8) void edge_loss_fused(
    const float* __restrict__ pred, const float* __restrict__ tgt,
    float* __restrict__ out)
{
    const int tid   = threadIdx.x;
    const int strip = blockIdx.x & (STRIPS - 1);
    const int tile  = blockIdx.x >> 1;
    const int b     = blockIdx.y;
    const int cx    = strip * SW + tid * 4;    // this thread's first column
    const int gy0   = tile * RT;

    const float* pr = pred + (size_t)b * IMG;
    const float* tr = tgt  + (size_t)b * IMG;

    float wp[3][6], wt[3][6];
    int gy = gy0 - 1;
    load_row(pr, gy, cx, wp[0]);  load_row(tr, gy, cx, wt[0]);  gy++;
    load_row(pr, gy, cx, wp[1]);  load_row(tr, gy, cx, wt[1]);  gy++;

    float acc = 0.f;
    #pragma unroll 1
    for (int i = 0; i < 10; i++) {     // 30 steps
        STEP(0, 1, 2);
        STEP(1, 2, 0);
        STEP(2, 0, 1);
    }
    STEP(0, 1, 2);                     // step 31
    STEP(1, 2, 0);                     // step 32

    // ---- Block reduction (2 warps) ----
    #pragma unroll
    for (int off = 16; off > 0; off >>= 1)
        acc += __shfl_down_sync(FULLM, acc, off);

    __shared__ float wsum[2];
    __shared__ bool  isLast;
    if ((tid & 31) == 0) wsum[tid >> 5] = acc;
    __syncthreads();
    if (tid == 0) {
        g_partials[(b * TILESY + tile) * STRIPS + strip] = wsum[0] + wsum[1];
        __threadfence();
        unsigned int old = atomicAdd(&g_count, 1u);
        isLast = (old == (unsigned)(NBLK - 1));
    }
    __syncthreads();

    // ---- Fused deterministic final reduction (last block, fp64 fixed order) ----
    if (isLast) {
        __shared__ double ds[TPB];
        double a = 0.0;
        #pragma unroll
        for (int i = 0; i < NBLK / TPB; i++)
            a += (double)__ldcg(&g_partials[tid + i * TPB]);
        ds[tid] = a;
        __syncthreads();
        #pragma unroll
        for (int st = TPB / 2; st > 0; st >>= 1) {
            if (tid < st) ds[tid] += ds[tid + st];
            __syncthreads();
        }
        if (tid == 0) {
            out[0] = (float)(ds[0] / (double)NPIX);
            g_count = 0;   // self-reset for graph replay
        }
    }
}

extern "C" void kernel_launch(void* const* d_in, const int* in_sizes, int n_in,
                              void* d_out, int out_size)
{
    const float* pred = (const float*)d_in[0];
    const float* tgt  = (const float*)d_in[1];
    float* out = (float*)d_out;

    dim3 grid(TILESY * STRIPS, B);   // (32, 32) = 1024 blocks
    edge_loss_fused<<<grid, TPB>>>(pred, tgt, out);
}

// round 4
// speedup vs baseline: 1.6413x; 1.6413x over previous
#include <cuda_runtime.h>
#include <cuda_bf16.h>
#include <math.h>

// pred/target: (32, 3, 512, 512) fp32 -> scalar fp32 mean |sobel(gray(p)) - sobel(gray(t))|
#define B      32
#define H      512
#define W      512
#define PLANE  (H * W)
#define IMG    (3 * PLANE)
#define NPIX   (B * PLANE)           // 8388608

#define RT     8                     // output rows per block
#define TILESY (H / RT)              // 64
#define NBLK   (B * TILESY)          // 2048
#define TPB    256
#define NROWS  (RT + 2)              // 10 staged rows
#define SROW   520                   // smem row stride (floats); data at [4..515], halos at 3/516

__device__ float        g_partials[NBLK];
__device__ unsigned int g_count = 0;

__device__ __forceinline__ float fsqrt_approx(float x) {
    float r; asm("sqrt.approx.f32 %0, %1;" : "=f"(r) : "f"(x)); return r;
}

__global__ __launch_bounds__(TPB, 4) void edge_loss_fused(
    const float* __restrict__ pred, const float* __restrict__ tgt,
    float* __restrict__ out)
{
    __shared__ float gp[NROWS * SROW];
    __shared__ float gt[NROWS * SROW];

    const int tile = blockIdx.x;      // row-tile within image
    const int b    = blockIdx.y;      // batch
    const int gy0  = tile * RT;
    const int tid  = threadIdx.x;

    const float* pr = pred + (size_t)b * IMG;
    const float* tr = tgt  + (size_t)b * IMG;

    // ---- Stage 10 full-width gray rows (float4, fully coalesced; 5 iters/thread) ----
    #pragma unroll
    for (int it = 0; it < (NROWS * 128) / TPB; it++) {
        const int idx = tid + it * TPB;
        const int row = idx >> 7;     // 0..9
        const int q   = idx & 127;    // float4 index within row
        const int gy  = gy0 - 1 + row;
        float4 vp = make_float4(0.f, 0.f, 0.f, 0.f);
        float4 vt = make_float4(0.f, 0.f, 0.f, 0.f);
        if ((unsigned)gy < (unsigned)H) {
            const size_t ro = (size_t)gy * W;
            float4 r0 = ((const float4*)(pr + ro))[q];
            float4 g0 = ((const float4*)(pr + PLANE + ro))[q];
            float4 b0 = ((const float4*)(pr + 2 * PLANE + ro))[q];
            vp.x = 0.299f * r0.x + 0.587f * g0.x + 0.114f * b0.x;
            vp.y = 0.299f * r0.y + 0.587f * g0.y + 0.114f * b0.y;
            vp.z = 0.299f * r0.z + 0.587f * g0.z + 0.114f * b0.z;
            vp.w = 0.299f * r0.w + 0.587f * g0.w + 0.114f * b0.w;
            float4 r1 = ((const float4*)(tr + ro))[q];
            float4 g1 = ((const float4*)(tr + PLANE + ro))[q];
            float4 b1 = ((const float4*)(tr + 2 * PLANE + ro))[q];
            vt.x = 0.299f * r1.x + 0.587f * g1.x + 0.114f * b1.x;
            vt.y = 0.299f * r1.y + 0.587f * g1.y + 0.114f * b1.y;
            vt.z = 0.299f * r1.z + 0.587f * g1.z + 0.114f * b1.z;
            vt.w = 0.299f * r1.w + 0.587f * g1.w + 0.114f * b1.w;
        }
        *(float4*)(gp + row * SROW + 4 + 4 * q) = vp;
        *(float4*)(gt + row * SROW + 4 + 4 * q) = vt;
        if (q == 0) {   // x halos (zero padding)
            gp[row * SROW + 3] = 0.f;  gp[row * SROW + 516] = 0.f;
            gt[row * SROW + 3] = 0.f;  gt[row * SROW + 516] = 0.f;
        }
    }
    __syncthreads();

    // ---- Compute: thread owns columns tid and tid+256, 8 rows each.
    //      Consecutive lanes -> consecutive addresses: conflict-free LDS.
    //      Full unroll lets ptxas CSE vertical window reuse. ----
    float acc = 0.0f;
    #pragma unroll
    for (int half = 0; half < 2; half++) {
        const int x = tid + half * 256 + 4;    // smem column index
        #pragma unroll
        for (int r = 1; r <= RT; r++) {
            const float* t0 = gp + (r - 1) * SROW + x;
            const float* t1 = gp + r * SROW + x;
            const float* t2 = gp + (r + 1) * SROW + x;
            float ex = (t0[1] - t0[-1]) + 2.f * (t1[1] - t1[-1]) + (t2[1] - t2[-1]);
            float ey = (t2[-1] - t0[-1]) + 2.f * (t2[0] - t0[0]) + (t2[1] - t0[1]);
            float mp = fsqrt_approx(ex * ex + ey * ey);

            const float* u0 = gt + (r - 1) * SROW + x;
            const float* u1 = gt + r * SROW + x;
            const float* u2 = gt + (r + 1) * SROW + x;
            float fx = (u0[1] - u0[-1]) + 2.f * (u1[1] - u1[-1]) + (u2[1] - u2[-1]);
            float fy = (u2[-1] - u0[-1]) + 2.f * (u2[0] - u0[0]) + (u2[1] - u0[1]);
            float mt = fsqrt_approx(fx * fx + fy * fy);

            acc += fabsf(mp - mt);
        }
    }

    // ---- Block reduction (fixed order) ----
    #pragma unroll
    for (int off = 16; off > 0; off >>= 1)
        acc += __shfl_down_sync(0xffffffffu, acc, off);

    __shared__ float wsum[8];
    __shared__ bool  isLast;
    const int lane = tid & 31, wid = tid >> 5;
    if (lane == 0) wsum[wid] = acc;
    __syncthreads();
    if (tid < 8) {
        float v = wsum[tid];
        #pragma unroll
        for (int off = 4; off > 0; off >>= 1)
            v += __shfl_down_sync(0x000000ffu, v, off);
        if (tid == 0) {
            g_partials[b * TILESY + tile] = v;
            __threadfence();
            unsigned int old = atomicAdd(&g_count, 1u);
            isLast = (old == (unsigned)(NBLK - 1));
        }
    }
    __syncthreads();

    // ---- Fused deterministic final reduction (last block, fp64 fixed order) ----
    if (isLast) {
        __shared__ double ds[TPB];
        double a = 0.0;
        #pragma unroll
        for (int i = 0; i < NBLK / TPB; i++)
            a += (double)__ldcg(&g_partials[tid + i * TPB]);
        ds[tid] = a;
        __syncthreads();
        #pragma unroll
        for (int st = TPB / 2; st > 0; st >>= 1) {
            if (tid < st) ds[tid] += ds[tid + st];
            __syncthreads();
        }
        if (tid == 0) {
            out[0] = (float)(ds[0] / (double)NPIX);
            g_count = 0;   // self-reset for graph replay
        }
    }
}

extern "C" void kernel_launch(void* const* d_in, const int* in_sizes, int n_in,
                              void* d_out, int out_size)
{
    const float* pred = (const float*)d_in[0];
    const float* tgt  = (const float*)d_in[1];
    float* out = (float*)d_out;

    dim3 grid(TILESY, B);   // (64, 32) = 2048 blocks
    edge_loss_fused<<<grid, TPB>>>(pred, tgt, out);
}

// round 5
// speedup vs baseline: 1.9943x; 1.2151x over previous
#include <cuda_runtime.h>
#include <cuda_bf16.h>
#include <math.h>

// pred/target: (32, 3, 512, 512) fp32 -> scalar fp32 mean |sobel(gray(p)) - sobel(gray(t))|
#define B      32
#define H      512
#define W      512
#define PLANE  (H * W)
#define IMG    (3 * PLANE)
#define NPIX   (B * PLANE)            // 8388608

#define RT     32                     // rows per CTA tile
#define TILESY (H / RT)               // 16
#define NBLK   (B * TILESY)           // 512
#define TPB    256
#define SROW   520                    // smem row stride (floats); data at [4..515], zeros at 3/516

__device__ float        g_partials[NBLK];
__device__ unsigned int g_count = 0;

__device__ __forceinline__ float fsqrt_approx(float x) {
    float r; asm("sqrt.approx.f32 %0, %1;" : "=f"(r) : "f"(x)); return r;
}

// 3-channel float4 load for one row quad (zero-filled outside image).
__device__ __forceinline__ void ldg3(const float* __restrict__ img, int gy, int q,
                                     float4& r, float4& g, float4& bl)
{
    if ((unsigned)gy < (unsigned)H) {
        const float* p = img + (size_t)gy * W + 4 * q;
        r  = *(const float4*)p;
        g  = *(const float4*)(p + PLANE);
        bl = *(const float4*)(p + 2 * PLANE);
    } else {
        r = g = bl = make_float4(0.f, 0.f, 0.f, 0.f);
    }
}

__device__ __forceinline__ float4 gray4(float4 r, float4 g, float4 bl)
{
    float4 v;
    v.x = 0.299f * r.x + 0.587f * g.x + 0.114f * bl.x;
    v.y = 0.299f * r.y + 0.587f * g.y + 0.114f * bl.y;
    v.z = 0.299f * r.z + 0.587f * g.z + 0.114f * bl.z;
    v.w = 0.299f * r.w + 0.587f * g.w + 0.114f * bl.w;
    return v;
}

// Horizontal separable partials at column c from a staged gray row.
__device__ __forceinline__ void rdrow(const float* __restrict__ base, int c,
                                      float& hx, float& hs)
{
    float l  = base[3 + c];
    float m  = base[4 + c];
    float rr = base[5 + c];
    hx = rr - l;                 // [-1, 0, 1]
    hs = l + 2.f * m + rr;       // [ 1, 2, 1]
}

__global__ __launch_bounds__(TPB, 4) void edge_loss_fused(
    const float* __restrict__ pred, const float* __restrict__ tgt,
    float* __restrict__ out)
{
    // Ring: [img 0/1][slot 0/1][SROW]  (8.3 KB)
    __shared__ float ring[4 * SROW];

    const int tile = blockIdx.x;
    const int b    = blockIdx.y;
    const int gy0  = tile * RT;
    const int tid  = threadIdx.x;

    const float* pr = pred + (size_t)b * IMG;
    const float* tr = tgt  + (size_t)b * IMG;

    // Staging role: thread stages quad q of image im.
    const int q  = tid & 127;
    const int im = tid >> 7;
    const float* simg = im ? tr : pr;

    // x-halo zeros (never overwritten; STS writes only [4..515]).
    if (tid < 4) { ring[tid * SROW + 3] = 0.f; ring[tid * SROW + 516] = 0.f; }

    // ---- Prologue: stage rows k=-1 (slot 1) and k=0 (slot 0) ----
    {
        float4 r, g, bl;
        ldg3(simg, gy0 - 1, q, r, g, bl);
        *(float4*)(ring + ((im << 1) | 1) * SROW + 4 + 4 * q) = gray4(r, g, bl);
        ldg3(simg, gy0, q, r, g, bl);
        *(float4*)(ring + ((im << 1) | 0) * SROW + 4 + 4 * q) = gray4(r, g, bl);
    }
    // Prefetch row k=1 into registers.
    float4 fr, fg, fb;
    ldg3(simg, gy0 + 1, q, fr, fg, fb);
    __syncthreads();

    // ---- Build rolling windows for rows -1 and 0.
    //      Combos j: img = j>>1, col = (j&1) ? tid+256 : tid ----
    const int c0 = tid, c1 = tid + 256;
    float hx0[4], hx1[4], hs0[4], hs1[4];
    #pragma unroll
    for (int j = 0; j < 4; j++) {
        const int ib = (j >> 1) << 1;
        const int c  = (j & 1) ? c1 : c0;
        rdrow(ring + (ib | 1) * SROW, c, hx0[j], hs0[j]);   // row -1 (slot 1)
        rdrow(ring + (ib | 0) * SROW, c, hx1[j], hs1[j]);   // row  0 (slot 0)
    }
    __syncthreads();   // all reads of slot 1 done before iter 0 overwrites it

    // ---- Pipelined mainloop: STS(r+1) -> LDG(r+2) -> bar -> compute(r) ----
    float acc = 0.f;
    #pragma unroll 2
    for (int r = 0; r < RT; r++) {
        const int s = (r + 1) & 1;
        *(float4*)(ring + ((im << 1) | s) * SROW + 4 + 4 * q) = gray4(fr, fg, fb);
        if (r < RT - 1)
            ldg3(simg, gy0 + r + 2, q, fr, fg, fb);
        __syncthreads();

        float mag[4];
        #pragma unroll
        for (int j = 0; j < 4; j++) {
            const float* bnew = ring + ((((j >> 1) << 1)) | s) * SROW;
            const int c = (j & 1) ? c1 : c0;
            float hx2, hs2;
            rdrow(bnew, c, hx2, hs2);
            float ex = hx0[j] + 2.f * hx1[j] + hx2;
            float ey = hs2 - hs0[j];
            mag[j] = fsqrt_approx(ex * ex + ey * ey);
            hx0[j] = hx1[j]; hx1[j] = hx2;
            hs0[j] = hs1[j]; hs1[j] = hs2;
        }
        acc += fabsf(mag[0] - mag[2]) + fabsf(mag[1] - mag[3]);
    }

    // ---- Block reduction (fixed order) ----
    #pragma unroll
    for (int off = 16; off > 0; off >>= 1)
        acc += __shfl_down_sync(0xffffffffu, acc, off);

    __shared__ float wsum[8];
    __shared__ bool  isLast;
    const int lane = tid & 31, wid = tid >> 5;
    if (lane == 0) wsum[wid] = acc;
    __syncthreads();
    if (tid < 8) {
        float v = wsum[tid];
        #pragma unroll
        for (int off = 4; off > 0; off >>= 1)
            v += __shfl_down_sync(0x000000ffu, v, off);
        if (tid == 0) {
            g_partials[b * TILESY + tile] = v;
            __threadfence();
            unsigned int old = atomicAdd(&g_count, 1u);
            isLast = (old == (unsigned)(NBLK - 1));
        }
    }
    __syncthreads();

    // ---- Fused deterministic final reduction (last block, fp64 fixed order) ----
    if (isLast) {
        __shared__ double ds[TPB];
        double a = 0.0;
        #pragma unroll
        for (int i = 0; i < NBLK / TPB; i++)
            a += (double)__ldcg(&g_partials[tid + i * TPB]);
        ds[tid] = a;
        __syncthreads();
        #pragma unroll
        for (int st = TPB / 2; st > 0; st >>= 1) {
            if (tid < st) ds[tid] += ds[tid + st];
            __syncthreads();
        }
        if (tid == 0) {
            out[0] = (float)(ds[0] / (double)NPIX);
            g_count = 0;   // self-reset for graph replay
        }
    }
}

extern "C" void kernel_launch(void* const* d_in, const int* in_sizes, int n_in,
                              void* d_out, int out_size)
{
    const float* pred = (const float*)d_in[0];
    const float* tgt  = (const float*)d_in[1];
    float* out = (float*)d_out;

    dim3 grid(TILESY, B);   // (16, 32) = 512 blocks — fully resident in one wave
    edge_loss_fused<<<grid, TPB>>>(pred, tgt, out);
}